// round 7
// baseline (speedup 1.0000x reference)
#include <cuda_runtime.h>
#include <cuda_fp16.h>
#include <cstdint>

constexpr int M = 1024;
constexpr int N = 32768;
constexpr int K = 512;
constexpr float MARGIN = 0.3f;

constexpr int BM = 128, BN = 256, BK = 32;
constexpr int NCH = K / BK;              // 16
constexpr int NSTAGE = 3;
constexpr int ROWB = 80;                 // 64B data + 16B pad per k-chunk row (f16)

// dynamic smem layout
constexpr uint32_t OFF_LAB = 0;                          // 256 ints = 1KB
constexpr uint32_t OFF_A   = 1024;
constexpr uint32_t A_STAGE = BM * ROWB;                  // 10240
constexpr uint32_t OFF_B   = OFF_A + NSTAGE * A_STAGE;   // 31744
constexpr uint32_t B_STAGE = BN * ROWB;                  // 20480
constexpr uint32_t SMEM_TOTAL = OFF_B + NSTAGE * B_STAGE;   // 93184

__device__ float g_pos[M];
__device__ float g_neg[M];
__device__ __half g_Ah[M * K];
__device__ __half g_Bh[(size_t)N * K];

__device__ __forceinline__ float f_inf()  { return __int_as_float(0x7f800000); }
__device__ __forceinline__ float f_ninf() { return __int_as_float(0xff800000); }

__device__ __forceinline__ void atomicMinF(float* a, float v) {
    if (v >= 0.f) atomicMin((int*)a, __float_as_int(v));
    else          atomicMax((unsigned int*)a, __float_as_uint(v));
}
__device__ __forceinline__ void atomicMaxF(float* a, float v) {
    if (v >= 0.f) atomicMax((int*)a, __float_as_int(v));
    else          atomicMin((unsigned int*)a, __float_as_uint(v));
}

__device__ __forceinline__ uint32_t smem_u32(const void* p) {
    uint32_t a;
    asm("{ .reg .u64 t; cvta.to.shared.u64 t, %1; cvt.u32.u64 %0, t; }" : "=r"(a) : "l"(p));
    return a;
}
__device__ __forceinline__ void ldsm_x4(uint32_t* r, uint32_t addr) {
    asm volatile("ldmatrix.sync.aligned.m8n8.x4.shared.b16 {%0,%1,%2,%3}, [%4];"
                 : "=r"(r[0]), "=r"(r[1]), "=r"(r[2]), "=r"(r[3]) : "r"(addr));
}
// f16 accumulator variant: D is 2 regs (4 x f16), halves acc write bandwidth.
__device__ __forceinline__ void mma_f16(uint32_t* d, const uint32_t* a, const uint32_t* b) {
    asm volatile(
        "mma.sync.aligned.m16n8k16.row.col.f16.f16.f16.f16 "
        "{%0,%1}, {%2,%3,%4,%5}, {%6,%7}, {%0,%1};"
        : "+r"(d[0]), "+r"(d[1])
        : "r"(a[0]), "r"(a[1]), "r"(a[2]), "r"(a[3]), "r"(b[0]), "r"(b[1]));
}
__device__ __forceinline__ void cp_async16(uint32_t dst, const void* src) {
    asm volatile("cp.async.cg.shared.global [%0], [%1], 16;" :: "r"(dst), "l"(src));
}
__device__ __forceinline__ void cp_commit() {
    asm volatile("cp.async.commit_group;" ::: "memory");
}
template <int NG> __device__ __forceinline__ void cp_wait() {
    asm volatile("cp.async.wait_group %0;" :: "n"(NG) : "memory");
}

// Convert fp32 -> f16 scratch; also (re)init the per-row min/max arrays.
__global__ void tl_quant(const float* __restrict__ A, const float* __restrict__ B) {
    const int gid = blockIdx.x * blockDim.x + threadIdx.x;
    const int nth = gridDim.x * blockDim.x;
    if (gid < M) { g_pos[gid] = f_inf(); g_neg[gid] = f_ninf(); }
    for (int i = gid; i < M * K / 4; i += nth) {
        float4 v = *reinterpret_cast<const float4*>(A + (size_t)i * 4);
        __half2 lo = __floats2half2_rn(v.x, v.y);
        __half2 hi = __floats2half2_rn(v.z, v.w);
        *reinterpret_cast<uint2*>(g_Ah + (size_t)i * 4) =
            make_uint2(*(uint32_t*)&lo, *(uint32_t*)&hi);
    }
    for (size_t i = gid; i < (size_t)N * K / 4; i += nth) {
        float4 v = *reinterpret_cast<const float4*>(B + i * 4);
        __half2 lo = __floats2half2_rn(v.x, v.y);
        __half2 hi = __floats2half2_rn(v.z, v.w);
        *reinterpret_cast<uint2*>(g_Bh + i * 4) =
            make_uint2(*(uint32_t*)&lo, *(uint32_t*)&hi);
    }
}

__global__ __launch_bounds__(512)
void tl_gemm(const int* __restrict__ targets, const int* __restrict__ idxv,
             const int* __restrict__ labels)
{
    extern __shared__ __align__(128) char smem[];
    __shared__ int   sT[BM];
    __shared__ int   sI[BM];
    __shared__ float sPos[BM];
    __shared__ float sNeg[BM];

    const uint32_t sb = smem_u32(smem);
    const uint32_t sA = sb + OFF_A;
    const uint32_t sB = sb + OFF_B;
    int* sLab = (int*)(smem + OFF_LAB);

    const int tid  = threadIdx.x;
    const int lane = tid & 31;
    const int wid  = tid >> 5;
    const int rowBase = blockIdx.y * BM;
    const int colBase = blockIdx.x * BN;

    // 16 warps: 4 (m) x 4 (n); warp tile 32 x 64
    const int warp_m = (wid >> 2) * 32;
    const int warp_n = (wid & 3) * 64;

    for (int i = tid; i < BN; i += 512) sLab[i] = labels[colBase + i];
    if (tid < BM) {
        sT[tid] = targets[rowBase + tid];
        sI[tid] = idxv[rowBase + tid];
        sPos[tid] = f_inf(); sNeg[tid] = f_ninf();
    }

    // per-stage cp.async loader: A = 512 x 16B chunks (1/thread), B = 1024 (2/thread)
    auto load_stage = [&](int st, int c) {
        const int kb = c * BK;
        const uint32_t dA = sA + st * A_STAGE;
        const uint32_t dB = sB + st * B_STAGE;
        {
            const int r = tid >> 2, q = tid & 3;
            cp_async16(dA + r * ROWB + q * 16,
                       g_Ah + (size_t)(rowBase + r) * K + kb + q * 8);
        }
#pragma unroll
        for (int i = 0; i < 2; ++i) {
            const int v = tid + i * 512;
            const int r = v >> 2, q = v & 3;
            cp_async16(dB + r * ROWB + q * 16,
                       g_Bh + (size_t)(colBase + r) * K + kb + q * 8);
        }
        cp_commit();
    };

    // ldmatrix lane offsets
    const uint32_t aOff = (uint32_t)(warp_m + (lane & 15)) * ROWB + (lane >> 4) * 16;
    const uint32_t bOff = (uint32_t)(warp_n + (lane & 7) + ((lane >> 4) * 8)) * ROWB
                        + ((lane >> 3) & 1) * 16;

    uint32_t acc[2][8][2] = {};   // f16x2 accumulators: [mi][ni][row-half]

    load_stage(0, 0);
    load_stage(1, 1);

#pragma unroll 1
    for (int c = 0; c < NCH; ++c) {
        if (c + 1 < NCH) cp_wait<1>(); else cp_wait<0>();
        __syncthreads();
        if (c + 2 < NCH) load_stage((c + 2) % NSTAGE, c + 2);

        const uint32_t stA = sA + (c % NSTAGE) * A_STAGE;
        const uint32_t stB = sB + (c % NSTAGE) * B_STAGE;
#pragma unroll
        for (int ks = 0; ks < 2; ++ks) {
            uint32_t af[2][4], bfr[4][4];
#pragma unroll
            for (int mi = 0; mi < 2; ++mi)
                ldsm_x4(af[mi], stA + aOff + mi * 16 * ROWB + ks * 32);
#pragma unroll
            for (int g = 0; g < 4; ++g)
                ldsm_x4(bfr[g], stB + bOff + g * 16 * ROWB + ks * 32);
#pragma unroll
            for (int mi = 0; mi < 2; ++mi)
#pragma unroll
                for (int ni = 0; ni < 8; ++ni)
                    mma_f16(acc[mi][ni], af[mi], &bfr[ni >> 1][(ni & 1) * 2]);
        }
    }
    __syncthreads();

    // Epilogue: unpack f16 accumulators, masked min/max per owned element.
    const int lq = lane >> 2;
    const int lr = (lane & 3) * 2;
#pragma unroll
    for (int mi = 0; mi < 2; ++mi) {
#pragma unroll
        for (int h = 0; h < 2; ++h) {
            const int rloc = warp_m + mi * 16 + h * 8 + lq;
            const int tg = sT[rloc];
            const int ix = sI[rloc];
            float pmin = f_inf(), nmax = f_ninf();
#pragma unroll
            for (int ni = 0; ni < 8; ++ni) {
                const float2 f2 = __half22float2(
                    *reinterpret_cast<const __half2*>(&acc[mi][ni][h]));
#pragma unroll
                for (int j = 0; j < 2; ++j) {
                    const int cloc = warp_n + ni * 8 + lr + j;
                    const float v = (j == 0) ? f2.x : f2.y;
                    if (sLab[cloc] == tg) {
                        if (colBase + cloc != ix) pmin = fminf(pmin, v);
                    } else {
                        nmax = fmaxf(nmax, v);
                    }
                }
            }
            atomicMinF(&sPos[rloc], pmin);
            atomicMaxF(&sNeg[rloc], nmax);
        }
    }
    __syncthreads();

    if (tid < BM) {
        const float p = sPos[tid], q = sNeg[tid];
        if (p <  f_inf())  atomicMinF(&g_pos[rowBase + tid], p);
        if (q > f_ninf())  atomicMaxF(&g_neg[rowBase + tid], q);
    }
}

__global__ void tl_final(float* __restrict__ out) {
    __shared__ float red[32];
    const int i = threadIdx.x;
    float l = fmaxf(g_neg[i] - g_pos[i] + MARGIN, 0.0f);
#pragma unroll
    for (int o = 16; o > 0; o >>= 1) l += __shfl_xor_sync(0xffffffffu, l, o);
    if ((i & 31) == 0) red[i >> 5] = l;
    __syncthreads();
    if (i < 32) {
        float s = red[i];
#pragma unroll
        for (int o = 16; o > 0; o >>= 1) s += __shfl_xor_sync(0xffffffffu, s, o);
        if (i == 0) out[0] = s * (1.0f / (float)M);
    }
}

extern "C" void kernel_launch(void* const* d_in, const int* in_sizes, int n_in,
                              void* d_out, int out_size) {
    const float* A       = (const float*)d_in[0];
    const float* B       = (const float*)d_in[1];
    const int*   targets = (const int*)  d_in[2];
    const int*   idxv    = (const int*)  d_in[3];
    const int*   labels  = (const int*)  d_in[4];
    float*       out     = (float*)d_out;

    static bool attrSet = false;
    if (!attrSet) {
        cudaFuncSetAttribute(tl_gemm, cudaFuncAttributeMaxDynamicSharedMemorySize,
                             SMEM_TOTAL);
        attrSet = true;
    }

    tl_quant<<<1024, 256>>>(A, B);
    dim3 grid(N / BN, M / BM);   // 128 x 8 = 1024 CTAs
    tl_gemm<<<grid, 512, SMEM_TOTAL>>>(targets, idxv, labels);
    tl_final<<<1, M>>>(out);
}

// round 8
// speedup vs baseline: 1.0832x; 1.0832x over previous
#include <cuda_runtime.h>
#include <cuda_bf16.h>
#include <cstdint>

constexpr int M = 1024;
constexpr int N = 32768;
constexpr int K = 512;
constexpr float MARGIN = 0.3f;

constexpr int BM = 128, BN = 256, BK = 32;
constexpr int NCH = K / BK;              // 16
constexpr int ROWB = 80;                 // 64B bf16 data + 16B pad per k-chunk row

// dynamic smem layout (double buffered)
constexpr uint32_t OFF_LAB = 0;                          // 256 ints = 1KB
constexpr uint32_t OFF_A   = 1024;
constexpr uint32_t A_STAGE = BM * ROWB;                  // 10240
constexpr uint32_t OFF_B   = OFF_A + 2 * A_STAGE;        // 21504
constexpr uint32_t B_STAGE = BN * ROWB;                  // 20480
constexpr uint32_t SMEM_TOTAL = OFF_B + 2 * B_STAGE;     // 62464

// per-row results in ordered-uint encoding:
//   enc(f) monotonic increasing; min-float == min-uint.
//   g_posU init = 0xFFFFFFFF (memset 0xFF), g_negU init = 0x00000000 (memset 0x00)
__device__ unsigned g_posU[M];
__device__ unsigned g_negU[M];

__device__ __forceinline__ float f_inf()  { return __int_as_float(0x7f800000); }
__device__ __forceinline__ float f_ninf() { return __int_as_float(0xff800000); }

__device__ __forceinline__ unsigned encOrd(float f) {
    unsigned b = __float_as_uint(f);
    return (b & 0x80000000u) ? ~b : (b | 0x80000000u);
}
__device__ __forceinline__ float decOrd(unsigned u) {
    return (u & 0x80000000u) ? __uint_as_float(u ^ 0x80000000u)
                             : __uint_as_float(~u);
}

__device__ __forceinline__ uint32_t smem_u32(const void* p) {
    uint32_t a;
    asm("{ .reg .u64 t; cvta.to.shared.u64 t, %1; cvt.u32.u64 %0, t; }" : "=r"(a) : "l"(p));
    return a;
}
__device__ __forceinline__ void ldsm_x4(uint32_t* r, uint32_t addr) {
    asm volatile("ldmatrix.sync.aligned.m8n8.x4.shared.b16 {%0,%1,%2,%3}, [%4];"
                 : "=r"(r[0]), "=r"(r[1]), "=r"(r[2]), "=r"(r[3]) : "r"(addr));
}
__device__ __forceinline__ void mma_bf16(float* d, const uint32_t* a, const uint32_t* b) {
    asm volatile(
        "mma.sync.aligned.m16n8k16.row.col.f32.bf16.bf16.f32 "
        "{%0,%1,%2,%3}, {%4,%5,%6,%7}, {%8,%9}, {%0,%1,%2,%3};"
        : "+f"(d[0]), "+f"(d[1]), "+f"(d[2]), "+f"(d[3])
        : "r"(a[0]), "r"(a[1]), "r"(a[2]), "r"(a[3]), "r"(b[0]), "r"(b[1]));
}
__device__ __forceinline__ void sts64_bf16(uint32_t addr, float4 v) {
    __nv_bfloat162 lo = __float22bfloat162_rn(make_float2(v.x, v.y));
    __nv_bfloat162 hi = __float22bfloat162_rn(make_float2(v.z, v.w));
    asm volatile("st.shared.v2.u32 [%0], {%1, %2};"
                 :: "r"(addr), "r"(*(uint32_t*)&lo), "r"(*(uint32_t*)&hi));
}

__global__ __launch_bounds__(512, 1)
void tl_gemm(const float* __restrict__ A, const float* __restrict__ B,
             const int* __restrict__ targets, const int* __restrict__ idxv,
             const int* __restrict__ labels)
{
    extern __shared__ __align__(128) char smem[];
    __shared__ int      sT[BM];
    __shared__ int      sI[BM];
    __shared__ unsigned sPosU[BM];
    __shared__ unsigned sNegU[BM];

    const uint32_t sb = smem_u32(smem);
    const uint32_t sA = sb + OFF_A;
    const uint32_t sB = sb + OFF_B;
    int* sLab = (int*)(smem + OFF_LAB);

    const int tid  = threadIdx.x;
    const int lane = tid & 31;
    const int wid  = tid >> 5;
    const int rowBase = blockIdx.y * BM;
    const int colBase = blockIdx.x * BN;

    // 16 warps: 4 (m) x 4 (n); warp tile 32 x 64
    const int warp_m = (wid >> 2) * 32;
    const int warp_n = (wid & 3) * 64;

    for (int i = tid; i < BN; i += 512) sLab[i] = labels[colBase + i];
    if (tid < BM) {
        sT[tid] = targets[rowBase + tid];
        sI[tid] = idxv[rowBase + tid];
        sPosU[tid] = 0xFFFFFFFFu;
        sNegU[tid] = 0u;
    }

    // fp32 loader with inline bf16 conversion.
    // A: 1024 float4 per chunk (2/thread); B: 2048 float4 (4/thread).
    float4 rA[2], rB[4];
    auto ldg_stage = [&](int c) {
        const int kb = c * BK;
#pragma unroll
        for (int i = 0; i < 2; ++i) {
            const int v = tid + i * 512;
            const int r = v >> 3, q = v & 7;
            rA[i] = *reinterpret_cast<const float4*>(
                &A[(size_t)(rowBase + r) * K + kb + q * 4]);
        }
#pragma unroll
        for (int i = 0; i < 4; ++i) {
            const int v = tid + i * 512;
            const int r = v >> 3, q = v & 7;
            rB[i] = *reinterpret_cast<const float4*>(
                &B[(size_t)(colBase + r) * K + kb + q * 4]);
        }
    };
    auto sts_stage = [&](int st) {
        const uint32_t dA = sA + st * A_STAGE;
        const uint32_t dB = sB + st * B_STAGE;
#pragma unroll
        for (int i = 0; i < 2; ++i) {
            const int v = tid + i * 512;
            const int r = v >> 3, q = v & 7;
            sts64_bf16(dA + r * ROWB + q * 8, rA[i]);
        }
#pragma unroll
        for (int i = 0; i < 4; ++i) {
            const int v = tid + i * 512;
            const int r = v >> 3, q = v & 7;
            sts64_bf16(dB + r * ROWB + q * 8, rB[i]);
        }
    };

    // ldmatrix lane offsets
    const uint32_t aOff = (uint32_t)(warp_m + (lane & 15)) * ROWB + (lane >> 4) * 16;
    const uint32_t bOff = (uint32_t)(warp_n + (lane & 7) + ((lane >> 4) & 1) * 8) * ROWB
                        + ((lane >> 3) & 1) * 16;

    float acc[2][8][4] = {};

    ldg_stage(0);
    sts_stage(0);
    __syncthreads();

#pragma unroll 1
    for (int c = 0; c < NCH; ++c) {
        if (c + 1 < NCH) ldg_stage(c + 1);

        const uint32_t stA = sA + (c & 1) * A_STAGE;
        const uint32_t stB = sB + (c & 1) * B_STAGE;
#pragma unroll
        for (int ks = 0; ks < 2; ++ks) {
            uint32_t af[2][4], bfr[4][4];
#pragma unroll
            for (int mi = 0; mi < 2; ++mi)
                ldsm_x4(af[mi], stA + aOff + mi * 16 * ROWB + ks * 32);
#pragma unroll
            for (int g = 0; g < 4; ++g)
                ldsm_x4(bfr[g], stB + bOff + g * 16 * ROWB + ks * 32);
#pragma unroll
            for (int mi = 0; mi < 2; ++mi)
#pragma unroll
                for (int ni = 0; ni < 8; ++ni)
                    mma_bf16(acc[mi][ni], af[mi], &bfr[ni >> 1][(ni & 1) * 2]);
        }

        if (c + 1 < NCH) sts_stage((c + 1) & 1);
        __syncthreads();
    }

    // Epilogue: masked min/max with ordered-uint atomics.
    const int lq = lane >> 2;
    const int lr = (lane & 3) * 2;
#pragma unroll
    for (int mi = 0; mi < 2; ++mi) {
#pragma unroll
        for (int h = 0; h < 2; ++h) {
            const int rloc = warp_m + mi * 16 + h * 8 + lq;
            const int tg = sT[rloc];
            const int ix = sI[rloc];
            float pmin = f_inf(), nmax = f_ninf();
#pragma unroll
            for (int ni = 0; ni < 8; ++ni) {
#pragma unroll
                for (int j = 0; j < 2; ++j) {
                    const int cloc = warp_n + ni * 8 + lr + j;
                    const float v = acc[mi][ni][h * 2 + j];
                    if (sLab[cloc] == tg) {
                        if (colBase + cloc != ix) pmin = fminf(pmin, v);
                    } else {
                        nmax = fmaxf(nmax, v);
                    }
                }
            }
            if (pmin <  f_inf())  atomicMin(&sPosU[rloc], encOrd(pmin));
            if (nmax > f_ninf())  atomicMax(&sNegU[rloc], encOrd(nmax));
        }
    }
    __syncthreads();

    if (tid < BM) {
        const unsigned p = sPosU[tid], q = sNegU[tid];
        if (p != 0xFFFFFFFFu) atomicMin(&g_posU[rowBase + tid], p);
        if (q != 0u)          atomicMax(&g_negU[rowBase + tid], q);
    }
}

__global__ void tl_final(float* __restrict__ out) {
    __shared__ float red[32];
    const int i = threadIdx.x;
    const float pos = decOrd(g_posU[i]);   // untouched rows -> NaN; fmaxf handles
    const float neg = decOrd(g_negU[i]);
    float l = fmaxf(neg - pos + MARGIN, 0.0f);
#pragma unroll
    for (int o = 16; o > 0; o >>= 1) l += __shfl_xor_sync(0xffffffffu, l, o);
    if ((i & 31) == 0) red[i >> 5] = l;
    __syncthreads();
    if (i < 32) {
        float s = red[i];
#pragma unroll
        for (int o = 16; o > 0; o >>= 1) s += __shfl_xor_sync(0xffffffffu, s, o);
        if (i == 0) out[0] = s * (1.0f / (float)M);
    }
}

extern "C" void kernel_launch(void* const* d_in, const int* in_sizes, int n_in,
                              void* d_out, int out_size) {
    const float* A       = (const float*)d_in[0];
    const float* B       = (const float*)d_in[1];
    const int*   targets = (const int*)  d_in[2];
    const int*   idxv    = (const int*)  d_in[3];
    const int*   labels  = (const int*)  d_in[4];
    float*       out     = (float*)d_out;

    static bool attrSet = false;
    if (!attrSet) {
        cudaFuncSetAttribute(tl_gemm, cudaFuncAttributeMaxDynamicSharedMemorySize,
                             SMEM_TOTAL);
        attrSet = true;
    }

    void *pPos = nullptr, *pNeg = nullptr;
    cudaGetSymbolAddress(&pPos, g_posU);
    cudaGetSymbolAddress(&pNeg, g_negU);
    cudaMemsetAsync(pPos, 0xFF, M * sizeof(unsigned));   // min-identity
    cudaMemsetAsync(pNeg, 0x00, M * sizeof(unsigned));   // max-identity

    dim3 grid(N / BN, M / BM);   // 128 x 8 = 1024 CTAs
    tl_gemm<<<grid, 512, SMEM_TOTAL>>>(A, B, targets, idxv, labels);
    tl_final<<<1, M>>>(out);
}